// round 12
// baseline (speedup 1.0000x reference)
#include <cuda_runtime.h>
#include <cuda_fp16.h>
#include <cstdint>

#define DH 512
#define KMAX 768
#define NODES_MAX 50048
#define EDGES_MAX 500000
#define BN_EPS 1e-5f

// ---------------- device scratch ----------------
__device__ __align__(16) __half g_Y[(size_t)NODES_MAX * DH];             // fp16 gather source
__device__ __align__(16) __half g_A2[(size_t)NODES_MAX * KMAX];          // fp16 activations
__device__ __align__(16) __half g_A2b[(size_t)NODES_MAX * DH];           // fp16 activations (512)
__device__ __align__(16) __half g_B2[4][(size_t)DH * KMAX];              // W^T [512, K] fp16
__device__ int g_deg[NODES_MAX + 1];
__device__ int g_offs[NODES_MAX + 2];
__device__ int g_cursor[NODES_MAX + 1];
__device__ int g_csr[EDGES_MAX];
__device__ int g_bsum[64];
__device__ int g_boff[64];
__device__ int g_is64;

// ---------------- PTX helpers ----------------
__device__ __forceinline__ uint32_t smem_u32(const void* p) {
    uint32_t a;
    asm("{ .reg .u64 t; cvta.to.shared.u64 t, %1; cvt.u32.u64 %0, t; }" : "=r"(a) : "l"(p));
    return a;
}
#define CP_ASYNC16(dst, src) \
    asm volatile("cp.async.cg.shared.global [%0], [%1], 16;" :: "r"(dst), "l"(src))
#define CP_COMMIT() asm volatile("cp.async.commit_group;" ::: "memory")
#define CP_WAIT1() asm volatile("cp.async.wait_group 1;" ::: "memory")
#define CP_WAIT_ALL() asm volatile("cp.async.wait_group 0;" ::: "memory")

#define LDMX4(r0, r1, r2, r3, addr)                                            \
    asm volatile("ldmatrix.sync.aligned.m8n8.x4.shared.b16 {%0,%1,%2,%3}, [%4];" \
                 : "=r"(r0), "=r"(r1), "=r"(r2), "=r"(r3) : "r"(addr))

#define MMA16816(d, a, b)                                                      \
    asm volatile(                                                              \
        "mma.sync.aligned.m16n8k16.row.col.f32.f16.f16.f32 "                   \
        "{%0,%1,%2,%3}, {%4,%5,%6,%7}, {%8,%9}, {%0,%1,%2,%3};"                \
        : "+f"((d)[0]), "+f"((d)[1]), "+f"((d)[2]), "+f"((d)[3])               \
        : "r"((a)[0]), "r"((a)[1]), "r"((a)[2]), "r"((a)[3]),                  \
          "r"((b)[0]), "r"((b)[1]))

// ---------------- edge-index dtype detection ----------------
__global__ void k_detect(const unsigned* __restrict__ w, int E) {
    __shared__ int ok;
    if (threadIdx.x == 0) ok = 1;
    __syncthreads();
    int n = min(E, 4096);
    for (int i = threadIdx.x; i < n; i += blockDim.x)
        if (w[2 * i + 1] != 0u) atomicAnd(&ok, 0);
    __syncthreads();
    if (threadIdx.x == 0) g_is64 = ok;
}
__device__ __forceinline__ void load_edge(const void* ei, int e, int E, int& s, int& d) {
    if (g_is64) {
        const long long* p = (const long long*)ei;
        s = (int)p[e];
        d = (int)p[(long long)E + e];
    } else {
        const int* p = (const int*)ei;
        s = p[e];
        d = p[E + e];
    }
}

// ---------------- setup: zero deg + out = bout ----------------
__global__ void k_setup(float* __restrict__ out, const float* __restrict__ bout, int M) {
    int i = blockIdx.x * blockDim.x + threadIdx.x;
    if (i < M) g_deg[i] = 0;
    if (i < 2 * M) out[i] = bout[i & 1];
}

// ---------------- CSR build ----------------
__global__ void k_count(const void* ei, int E) {
    int e = blockIdx.x * blockDim.x + threadIdx.x;
    if (e >= E) return;
    int s, d;
    load_edge(ei, e, E, s, d);
    atomicAdd(&g_deg[d], 1);
}
__global__ void k_scan1(int N) {
    __shared__ int sm[1024];
    int b = blockIdx.x, t = threadIdx.x, i = b * 1024 + t;
    int v = (i < N) ? g_deg[i] : 0;
    sm[t] = v;
    __syncthreads();
    for (int off = 1; off < 1024; off <<= 1) {
        int x = (t >= off) ? sm[t - off] : 0;
        __syncthreads();
        sm[t] += x;
        __syncthreads();
    }
    if (i < N) g_offs[i] = sm[t] - v;
    if (t == 1023) g_bsum[b] = sm[1023];
}
__global__ void k_scan2(int NB) {
    if (threadIdx.x == 0) {
        int r = 0;
        for (int b = 0; b < NB; b++) { g_boff[b] = r; r += g_bsum[b]; }
    }
}
__global__ void k_scan3(int N, int E) {
    int b = blockIdx.x, t = threadIdx.x, i = b * 1024 + t;
    if (i < N) {
        int o = g_offs[i] + g_boff[b];
        g_offs[i] = o;
        g_cursor[i] = o;
    }
    if (i == 0) g_offs[N] = E;
}
__global__ void k_fill(const void* ei, int E) {
    int e = blockIdx.x * blockDim.x + threadIdx.x;
    if (e >= E) return;
    int s, d;
    load_edge(ei, e, E, s, d);
    int pos = atomicAdd(&g_cursor[d], 1);
    g_csr[pos] = s;
}

// ---------------- fp16 conversions ----------------
__global__ void k_convA(const float* __restrict__ A, __half* __restrict__ A2, int M, int K) {
    int K4 = K >> 2;
    int i = blockIdx.x * blockDim.x + threadIdx.x;
    if (i >= M * K4) return;
    int row = i / K4, c = (i - row * K4) << 2;
    float4 v = *(const float4*)(A + (size_t)row * K + c);
    __half2* p = (__half2*)(A2 + (size_t)row * K + c);
    p[0] = __floats2half2_rn(v.x, v.y);
    p[1] = __floats2half2_rn(v.z, v.w);
}

// all 4 weights in one launch: W1a [K1,512], then W1b/W2a/W2b [512,512]
__global__ void k_convW_all(const float* __restrict__ W1a, const float* __restrict__ W1b,
                            const float* __restrict__ W2a, const float* __restrict__ W2b,
                            __half* __restrict__ B2base, int K1) {
    int i = blockIdx.x * blockDim.x + threadIdx.x;
    int n1 = K1 * 512;
    int total = n1 + 3 * 512 * 512;
    if (i >= total) return;
    const float* W;
    __half* B2;
    int K, j;
    if (i < n1) {
        W = W1a; K = K1; B2 = B2base; j = i;
    } else {
        int t = i - n1;
        int w = t / (512 * 512);
        j = t - w * 512 * 512;
        K = 512;
        W = (w == 0) ? W1b : (w == 1) ? W2a : W2b;
        B2 = B2base + (size_t)(w + 1) * DH * KMAX;
    }
    int k = j / 512, n = j - k * 512;
    B2[(size_t)n * K + k] = __float2half_rn(W[j]);
}

// ---------------- HMMA GEMM: single-pass fp16, 3-stage cp.async pipeline ----------------
#define LDSS 144
#define STAGE_BYTES (128 * LDSS)
#define NSTAGE 3
#define DSM_REQ (2 * NSTAGE * STAGE_BYTES)   // 110592

__device__ __forceinline__ void fill_stage(uint32_t sA, uint32_t sB,
                                           const __half* A2, const __half* B2,
                                           int m0, int n0, int ko,
                                           int ldk, int M, int tid) {
#pragma unroll
    for (int i = 0; i < 4; i++) {
        int G = tid + i * 256;
        int row = G >> 3, c = G & 7;
        int gr = m0 + row;
        if (gr >= M) gr = M - 1;
        const char* src = (const char*)(A2 + (size_t)gr * ldk + ko) + c * 16;
        CP_ASYNC16(sA + row * LDSS + c * 16, src);
    }
#pragma unroll
    for (int i = 0; i < 4; i++) {
        int G = tid + i * 256;
        int row = G >> 3, c = G & 7;
        const char* src = (const char*)(B2 + (size_t)(n0 + row) * ldk + ko) + c * 16;
        CP_ASYNC16(sB + row * LDSS + c * 16, src);
    }
}

// EPI=0: Y = fp16(acc).
// EPI=1: v = relu(acc+bias); if WA2: fp16 v -> A2out; if HEAD: out += v x Wout (atomics).
template <int EPI, int WA2, int HEAD>
__global__ __launch_bounds__(256, 2) void k_gemm_mma(
    const __half* __restrict__ A2, const __half* __restrict__ B2,
    const float* __restrict__ bias, __half* __restrict__ Y,
    __half* __restrict__ A2out, const float* __restrict__ Wout,
    float* __restrict__ out, int M, int K) {
    extern __shared__ char dsm[];
    int tid = threadIdx.x, lane = tid & 31, warp = tid >> 5;
    int wm = warp >> 1, wn = warp & 1;
    int m0 = blockIdx.y * 128, n0 = blockIdx.x * 128;
    int nch = K >> 6;

    uint32_t base = smem_u32(dsm);
    uint32_t sA[NSTAGE], sB[NSTAGE];
#pragma unroll
    for (int i = 0; i < NSTAGE; i++) {
        sA[i] = base + i * STAGE_BYTES;
        sB[i] = base + (NSTAGE + i) * STAGE_BYTES;
    }

    float acc[2][8][4];
#pragma unroll
    for (int a = 0; a < 2; a++)
#pragma unroll
        for (int b = 0; b < 8; b++)
#pragma unroll
            for (int k = 0; k < 4; k++) acc[a][b][k] = 0.f;

    // prologue: prefetch chunks 0, 1
    fill_stage(sA[0], sB[0], A2, B2, m0, n0, 0, K, M, tid);
    CP_COMMIT();
    fill_stage(sA[1], sB[1], A2, B2, m0, n0, 64, K, M, tid);
    CP_COMMIT();

    int tile = lane >> 3, r = lane & 7;

    for (int c = 0; c < nch; c++) {
        int s = c % NSTAGE;
        if (c + 1 < nch) CP_WAIT1(); else CP_WAIT_ALL();   // chunk c resident
        __syncthreads();
        if (c + 2 < nch) {
            int sn = (c + 2) % NSTAGE;
            fill_stage(sA[sn], sB[sn], A2, B2, m0, n0, (c + 2) * 64, K, M, tid);
            CP_COMMIT();
        }
#pragma unroll
        for (int kk = 0; kk < 4; kk++) {
            uint32_t af[2][4];
#pragma unroll
            for (int am = 0; am < 2; am++) {
                int trow = wm * 32 + am * 16 + (tile & 1) * 8 + r;
                uint32_t addr = sA[s] + trow * LDSS + kk * 32 + (tile >> 1) * 16;
                LDMX4(af[am][0], af[am][1], af[am][2], af[am][3], addr);
            }
            uint32_t bf[8][2];
#pragma unroll
            for (int bn = 0; bn < 4; bn++) {
                int trow = wn * 64 + bn * 16 + (tile >> 1) * 8 + r;
                uint32_t addr = sB[s] + trow * LDSS + kk * 32 + (tile & 1) * 16;
                LDMX4(bf[2 * bn][0], bf[2 * bn][1], bf[2 * bn + 1][0], bf[2 * bn + 1][1], addr);
            }
#pragma unroll
            for (int am = 0; am < 2; am++)
#pragma unroll
                for (int bn = 0; bn < 8; bn++) MMA16816(acc[am][bn], af[am], bf[bn]);
        }
        __syncthreads();
    }

    // epilogue (all lanes execute; stores/atomics predicated on valid)
#pragma unroll
    for (int am = 0; am < 2; am++) {
        int r0 = m0 + wm * 32 + am * 16 + (lane >> 2);
#pragma unroll
        for (int half = 0; half < 2; half++) {
            int row = r0 + half * 8;
            bool valid = row < M;
            float s0 = 0.f, s1 = 0.f;
#pragma unroll
            for (int bn = 0; bn < 8; bn++) {
                int col = n0 + wn * 64 + bn * 8 + (lane & 3) * 2;
                float v0 = acc[am][bn][2 * half], v1 = acc[am][bn][2 * half + 1];
                if (EPI == 0) {
                    if (valid)
                        *(__half2*)(Y + (size_t)row * DH + col) = __floats2half2_rn(v0, v1);
                } else {
                    float2 bs = *(const float2*)(bias + col);
                    v0 = fmaxf(v0 + bs.x, 0.f);
                    v1 = fmaxf(v1 + bs.y, 0.f);
                    if (WA2 && valid)
                        *(__half2*)(A2out + (size_t)row * DH + col) = __floats2half2_rn(v0, v1);
                    if (HEAD) {
                        float4 w = *(const float4*)(Wout + 2 * col);
                        s0 = fmaf(v0, w.x, fmaf(v1, w.z, s0));
                        s1 = fmaf(v0, w.y, fmaf(v1, w.w, s1));
                    }
                }
            }
            if (HEAD) {
                s0 += __shfl_xor_sync(0xffffffffu, s0, 1);
                s0 += __shfl_xor_sync(0xffffffffu, s0, 2);
                s1 += __shfl_xor_sync(0xffffffffu, s1, 1);
                s1 += __shfl_xor_sync(0xffffffffu, s1, 2);
                if (valid && (lane & 3) == 0) {
                    atomicAdd(out + 2 * row, s0);
                    atomicAdd(out + 2 * row + 1, s1);
                }
            }
        }
    }
}

// ---------------- fused aggregation (fp16 gather, fp32 accum) + bias + BN + ReLU -> fp16 ----------------
__global__ void k_agg(const __half* __restrict__ Y, const float* __restrict__ bias,
                      const float* __restrict__ gamma, const float* __restrict__ beta,
                      const float* __restrict__ mean, const float* __restrict__ var,
                      __half* __restrict__ A2out) {
    int n = blockIdx.x, t = threadIdx.x;
    int c = t * 4;
    int beg = g_offs[n], end = g_offs[n + 1];
    float4 acc;
    {
        uint2 raw = *(const uint2*)(Y + (size_t)n * DH + c);
        float2 a = __half22float2(*(__half2*)&raw.x);
        float2 b = __half22float2(*(__half2*)&raw.y);
        acc = make_float4(a.x, a.y, b.x, b.y);
    }
    float4 bs = *(const float4*)(bias + c);
    acc.x += bs.x; acc.y += bs.y; acc.z += bs.z; acc.w += bs.w;
    int i = beg;
    for (; i + 4 <= end; i += 4) {
        int s0 = g_csr[i], s1 = g_csr[i + 1], s2 = g_csr[i + 2], s3 = g_csr[i + 3];
        uint2 r0 = *(const uint2*)(Y + (size_t)s0 * DH + c);
        uint2 r1 = *(const uint2*)(Y + (size_t)s1 * DH + c);
        uint2 r2 = *(const uint2*)(Y + (size_t)s2 * DH + c);
        uint2 r3 = *(const uint2*)(Y + (size_t)s3 * DH + c);
        float2 a0 = __half22float2(*(__half2*)&r0.x), b0 = __half22float2(*(__half2*)&r0.y);
        float2 a1 = __half22float2(*(__half2*)&r1.x), b1 = __half22float2(*(__half2*)&r1.y);
        float2 a2 = __half22float2(*(__half2*)&r2.x), b2 = __half22float2(*(__half2*)&r2.y);
        float2 a3 = __half22float2(*(__half2*)&r3.x), b3 = __half22float2(*(__half2*)&r3.y);
        acc.x += (a0.x + a1.x) + (a2.x + a3.x);
        acc.y += (a0.y + a1.y) + (a2.y + a3.y);
        acc.z += (b0.x + b1.x) + (b2.x + b3.x);
        acc.w += (b0.y + b1.y) + (b2.y + b3.y);
    }
    for (; i < end; i++) {
        int s = g_csr[i];
        uint2 raw = *(const uint2*)(Y + (size_t)s * DH + c);
        float2 a = __half22float2(*(__half2*)&raw.x);
        float2 b = __half22float2(*(__half2*)&raw.y);
        acc.x += a.x; acc.y += a.y; acc.z += b.x; acc.w += b.y;
    }
    float4 mn = *(const float4*)(mean + c);
    float4 vr = *(const float4*)(var + c);
    float4 gm = *(const float4*)(gamma + c);
    float4 bt = *(const float4*)(beta + c);
    acc.x = fmaxf(fmaf((acc.x - mn.x) * rsqrtf(vr.x + BN_EPS), gm.x, bt.x), 0.f);
    acc.y = fmaxf(fmaf((acc.y - mn.y) * rsqrtf(vr.y + BN_EPS), gm.y, bt.y), 0.f);
    acc.z = fmaxf(fmaf((acc.z - mn.z) * rsqrtf(vr.z + BN_EPS), gm.z, bt.z), 0.f);
    acc.w = fmaxf(fmaf((acc.w - mn.w) * rsqrtf(vr.w + BN_EPS), gm.w, bt.w), 0.f);
    __half2* p = (__half2*)(A2out + (size_t)n * DH + c);
    p[0] = __floats2half2_rn(acc.x, acc.y);
    p[1] = __floats2half2_rn(acc.z, acc.w);
}

// ---------------- launch ----------------
extern "C" void kernel_launch(void* const* d_in, const int* in_sizes, int n_in,
                              void* d_out, int out_size) {
    const float* x    = (const float*)d_in[0];
    const void*  ei   = d_in[1];
    const float* W1a  = (const float*)d_in[2];
    const float* b1a  = (const float*)d_in[3];
    const float* g1   = (const float*)d_in[4];
    const float* be1  = (const float*)d_in[5];
    const float* m1   = (const float*)d_in[6];
    const float* v1   = (const float*)d_in[7];
    const float* W1b  = (const float*)d_in[8];
    const float* b1b  = (const float*)d_in[9];
    const float* W2a  = (const float*)d_in[10];
    const float* b2a  = (const float*)d_in[11];
    const float* g2   = (const float*)d_in[12];
    const float* be2  = (const float*)d_in[13];
    const float* m2   = (const float*)d_in[14];
    const float* v2   = (const float*)d_in[15];
    const float* W2b  = (const float*)d_in[16];
    const float* b2b  = (const float*)d_in[17];
    const float* Wout = (const float*)d_in[18];
    const float* bout = (const float*)d_in[19];
    float* out = (float*)d_out;

    int E = in_sizes[1] / 2;
    int K1 = in_sizes[2] / DH;  // 768
    int M = in_sizes[0] / K1;   // 50000

    __half *Y, *A2, *A2b, *B2base;
    cudaGetSymbolAddress((void**)&Y, g_Y);
    cudaGetSymbolAddress((void**)&A2, g_A2);
    cudaGetSymbolAddress((void**)&A2b, g_A2b);
    cudaGetSymbolAddress((void**)&B2base, g_B2);
    __half* B2_1a = B2base;
    __half* B2_1b = B2base + (size_t)DH * KMAX;
    __half* B2_2a = B2base + 2 * (size_t)DH * KMAX;
    __half* B2_2b = B2base + 3 * (size_t)DH * KMAX;

    cudaFuncSetAttribute(k_gemm_mma<0, 0, 0>, cudaFuncAttributeMaxDynamicSharedMemorySize, DSM_REQ);
    cudaFuncSetAttribute(k_gemm_mma<1, 1, 0>, cudaFuncAttributeMaxDynamicSharedMemorySize, DSM_REQ);
    cudaFuncSetAttribute(k_gemm_mma<1, 0, 1>, cudaFuncAttributeMaxDynamicSharedMemorySize, DSM_REQ);

    // weight conversions (one launch) + setup (deg zero + out=bout)
    int wtot = K1 * 512 + 3 * 512 * 512;
    k_convW_all<<<(wtot + 255) / 256, 256>>>(W1a, W1b, W2a, W2b, B2base, K1);
    k_setup<<<(2 * M + 255) / 256, 256>>>(out, bout, M);

    // CSR build
    k_detect<<<1, 1024>>>((const unsigned*)ei, E);
    k_count<<<(E + 255) / 256, 256>>>(ei, E);
    int NB = (M + 1023) / 1024;
    k_scan1<<<NB, 1024>>>(M);
    k_scan2<<<1, 32>>>(NB);
    k_scan3<<<NB, 1024>>>(M, E);
    k_fill<<<(E + 255) / 256, 256>>>(ei, E);

    dim3 gg(4, (M + 127) / 128);

    // Layer 1: (x + agg(x))@W1a + b1a == x@W1a + segsum((x@W1a)[src]) + b1a
    k_convA<<<(M * (K1 / 4) + 255) / 256, 256>>>(x, A2, M, K1);
    k_gemm_mma<0, 0, 0><<<gg, 256, DSM_REQ>>>(A2, B2_1a, nullptr, Y, nullptr, nullptr, nullptr, M, K1);
    k_agg<<<M, 128>>>(Y, b1a, g1, be1, m1, v1, A2b);
    k_gemm_mma<1, 1, 0><<<gg, 256, DSM_REQ>>>(A2b, B2_1b, b1b, nullptr, A2, nullptr, nullptr, M, DH);

    // Layer 2
    k_gemm_mma<0, 0, 0><<<gg, 256, DSM_REQ>>>(A2, B2_2a, nullptr, Y, nullptr, nullptr, nullptr, M, DH);
    k_agg<<<M, 128>>>(Y, b2a, g2, be2, m2, v2, A2b);
    // final GEMM: fused bias+ReLU+head (out += relu(acc+b) @ Wout)
    k_gemm_mma<1, 0, 1><<<gg, 256, DSM_REQ>>>(A2b, B2_2b, b2b, nullptr, nullptr, Wout, out, M, DH);
}

// round 14
// speedup vs baseline: 1.0474x; 1.0474x over previous
#include <cuda_runtime.h>
#include <cuda_fp16.h>
#include <cstdint>

#define DH 512
#define KMAX 768
#define NODES_MAX 50048
#define EDGES_MAX 500000
#define BN_EPS 1e-5f

// ---------------- device scratch ----------------
__device__ __align__(16) __half g_Y[(size_t)NODES_MAX * DH];             // fp16 gather source
__device__ __align__(16) __half g_A2[(size_t)NODES_MAX * KMAX];          // fp16 activations
__device__ __align__(16) __half g_A2b[(size_t)NODES_MAX * DH];           // fp16 activations (512)
__device__ __align__(16) __half g_B2[4][(size_t)DH * KMAX];              // W^T [512, K] fp16
__device__ int g_deg[NODES_MAX + 1];
__device__ int g_offs[NODES_MAX + 2];
__device__ int g_cursor[NODES_MAX + 1];
__device__ int g_csr[EDGES_MAX];
__device__ int g_bsum[64];
__device__ int g_is64;

// ---------------- PTX helpers ----------------
__device__ __forceinline__ uint32_t smem_u32(const void* p) {
    uint32_t a;
    asm("{ .reg .u64 t; cvta.to.shared.u64 t, %1; cvt.u32.u64 %0, t; }" : "=r"(a) : "l"(p));
    return a;
}
#define CP_ASYNC16(dst, src) \
    asm volatile("cp.async.cg.shared.global [%0], [%1], 16;" :: "r"(dst), "l"(src))
#define CP_COMMIT() asm volatile("cp.async.commit_group;" ::: "memory")
#define CP_WAIT_ALL() asm volatile("cp.async.wait_group 0;" ::: "memory")

#define LDMX4(r0, r1, r2, r3, addr)                                            \
    asm volatile("ldmatrix.sync.aligned.m8n8.x4.shared.b16 {%0,%1,%2,%3}, [%4];" \
                 : "=r"(r0), "=r"(r1), "=r"(r2), "=r"(r3) : "r"(addr))

#define MMA16816(d, a, b)                                                      \
    asm volatile(                                                              \
        "mma.sync.aligned.m16n8k16.row.col.f32.f16.f16.f32 "                   \
        "{%0,%1,%2,%3}, {%4,%5,%6,%7}, {%8,%9}, {%0,%1,%2,%3};"                \
        : "+f"((d)[0]), "+f"((d)[1]), "+f"((d)[2]), "+f"((d)[3])               \
        : "r"((a)[0]), "r"((a)[1]), "r"((a)[2]), "r"((a)[3]),                  \
          "r"((b)[0]), "r"((b)[1]))

// ---------------- edge helpers ----------------
__device__ __forceinline__ void load_edge(const void* ei, int e, int E, int& s, int& d) {
    if (g_is64) {
        const long long* p = (const long long*)ei;
        s = (int)p[e];
        d = (int)p[(long long)E + e];
    } else {
        const int* p = (const int*)ei;
        s = p[e];
        d = p[E + e];
    }
}

// ---------------- prep mega-kernel: detect | convW(all) | setup | convA(x) ----------------
__global__ void k_prep(const unsigned* __restrict__ ei_w, int E,
                       const float* __restrict__ W1a, const float* __restrict__ W1b,
                       const float* __restrict__ W2a, const float* __restrict__ W2b,
                       __half* __restrict__ B2base, int K1,
                       float* __restrict__ out, const float* __restrict__ bout,
                       const float* __restrict__ x, __half* __restrict__ A2, int M) {
    int b = blockIdx.x;
    int tid = threadIdx.x;
    if (b == 0) {
        // dtype detect: int64 positive ids < 2^31 => every odd 32-bit word is 0
        __shared__ int ok;
        if (tid == 0) ok = 1;
        __syncthreads();
        int n = min(E, 4096);
        for (int i = tid; i < n; i += blockDim.x)
            if (ei_w[2 * i + 1] != 0u) atomicAnd(&ok, 0);
        __syncthreads();
        if (tid == 0) g_is64 = ok;
        return;
    }
    b -= 1;
    int wtot = K1 * 512 + 3 * 512 * 512;
    int nbW = (wtot + 255) / 256;
    if (b < nbW) {
        int i = b * 256 + tid;
        if (i >= wtot) return;
        const float* W;
        __half* B2;
        int K, j;
        int n1 = K1 * 512;
        if (i < n1) {
            W = W1a; K = K1; B2 = B2base; j = i;
        } else {
            int t = i - n1;
            int w = t / (512 * 512);
            j = t - w * 512 * 512;
            K = 512;
            W = (w == 0) ? W1b : (w == 1) ? W2a : W2b;
            B2 = B2base + (size_t)(w + 1) * DH * KMAX;
        }
        int k = j / 512, n = j - k * 512;
        B2[(size_t)n * K + k] = __float2half_rn(W[j]);
        return;
    }
    b -= nbW;
    int nbS = (2 * M + 255) / 256;
    if (b < nbS) {
        int i = b * 256 + tid;
        if (i < M) g_deg[i] = 0;
        if (i < 2 * M) out[i] = bout[i & 1];
        return;
    }
    b -= nbS;
    // convA: fp32 x -> fp16 A2
    int K4 = K1 >> 2;
    int i = b * 256 + tid;
    if (i >= M * K4) return;
    int row = i / K4, c = (i - row * K4) << 2;
    float4 v = *(const float4*)(x + (size_t)row * K1 + c);
    __half2* p = (__half2*)(A2 + (size_t)row * K1 + c);
    p[0] = __floats2half2_rn(v.x, v.y);
    p[1] = __floats2half2_rn(v.z, v.w);
}

// ---------------- CSR build ----------------
__global__ void k_count(const void* ei, int E) {
    int e = blockIdx.x * blockDim.x + threadIdx.x;
    if (e >= E) return;
    int s, d;
    load_edge(ei, e, E, s, d);
    atomicAdd(&g_deg[d], 1);
}
__global__ void k_scan1(int N) {
    __shared__ int sm[1024];
    int b = blockIdx.x, t = threadIdx.x, i = b * 1024 + t;
    int v = (i < N) ? g_deg[i] : 0;
    sm[t] = v;
    __syncthreads();
    for (int off = 1; off < 1024; off <<= 1) {
        int x = (t >= off) ? sm[t - off] : 0;
        __syncthreads();
        sm[t] += x;
        __syncthreads();
    }
    if (i < N) g_offs[i] = sm[t] - v;
    if (t == 1023) g_bsum[b] = sm[1023];
}
// scan3 with inlined block-offset prefix (replaces scan2+scan3)
__global__ void k_scan3(int N, int E) {
    __shared__ int boff;
    int b = blockIdx.x, t = threadIdx.x, i = b * 1024 + t;
    if (t == 0) {
        int r = 0;
        for (int j = 0; j < b; j++) r += g_bsum[j];
        boff = r;
    }
    __syncthreads();
    if (i < N) {
        int o = g_offs[i] + boff;
        g_offs[i] = o;
        g_cursor[i] = o;
    }
    if (i == 0) g_offs[N] = E;
}
__global__ void k_fill(const void* ei, int E) {
    int e = blockIdx.x * blockDim.x + threadIdx.x;
    if (e >= E) return;
    int s, d;
    load_edge(ei, e, E, s, d);
    int pos = atomicAdd(&g_cursor[d], 1);
    g_csr[pos] = s;
}

// ---------------- HMMA GEMM (R11-proven): single-pass fp16, 2-stage cp.async ----------------
#define LDSS 144
#define STAGE_BYTES (128 * LDSS)
#define DSM_REQ (4 * STAGE_BYTES)

__device__ __forceinline__ void fill_stage(uint32_t sA, uint32_t sB,
                                           const __half* A2, const __half* B2,
                                           int m0, int n0, int ko,
                                           int ldk, int M, int tid) {
#pragma unroll
    for (int i = 0; i < 4; i++) {
        int G = tid + i * 256;
        int row = G >> 3, c = G & 7;
        int gr = m0 + row;
        if (gr >= M) gr = M - 1;
        const char* src = (const char*)(A2 + (size_t)gr * ldk + ko) + c * 16;
        CP_ASYNC16(sA + row * LDSS + c * 16, src);
    }
#pragma unroll
    for (int i = 0; i < 4; i++) {
        int G = tid + i * 256;
        int row = G >> 3, c = G & 7;
        const char* src = (const char*)(B2 + (size_t)(n0 + row) * ldk + ko) + c * 16;
        CP_ASYNC16(sB + row * LDSS + c * 16, src);
    }
}

// EPI=0: Y = fp16(acc).
// EPI=1: v = relu(acc+bias); if WA2: fp16 v -> A2out; if HEAD: out += v x Wout (atomics).
template <int EPI, int WA2, int HEAD>
__global__ __launch_bounds__(256, 2) void k_gemm_mma(
    const __half* __restrict__ A2, const __half* __restrict__ B2,
    const float* __restrict__ bias, __half* __restrict__ Y,
    __half* __restrict__ A2out, const float* __restrict__ Wout,
    float* __restrict__ out, int M, int K) {
    extern __shared__ char dsm[];
    int tid = threadIdx.x, lane = tid & 31, warp = tid >> 5;
    int wm = warp >> 1, wn = warp & 1;
    int m0 = blockIdx.y * 128, n0 = blockIdx.x * 128;
    int nch = K >> 6;

    uint32_t base = smem_u32(dsm);
    uint32_t sA[2] = {base, base + STAGE_BYTES};
    uint32_t sB[2] = {base + 2 * STAGE_BYTES, base + 3 * STAGE_BYTES};

    float acc[2][8][4];
#pragma unroll
    for (int a = 0; a < 2; a++)
#pragma unroll
        for (int b = 0; b < 8; b++)
#pragma unroll
            for (int k = 0; k < 4; k++) acc[a][b][k] = 0.f;

    fill_stage(sA[0], sB[0], A2, B2, m0, n0, 0, K, M, tid);
    CP_COMMIT();

    int tile = lane >> 3, r = lane & 7;

    for (int c = 0; c < nch; c++) {
        int s = c & 1;
        CP_WAIT_ALL();
        __syncthreads();
        if (c + 1 < nch) {
            fill_stage(sA[s ^ 1], sB[s ^ 1], A2, B2, m0, n0, (c + 1) * 64, K, M, tid);
            CP_COMMIT();
        }
#pragma unroll
        for (int kk = 0; kk < 4; kk++) {
            uint32_t af[2][4];
#pragma unroll
            for (int am = 0; am < 2; am++) {
                int trow = wm * 32 + am * 16 + (tile & 1) * 8 + r;
                uint32_t addr = sA[s] + trow * LDSS + kk * 32 + (tile >> 1) * 16;
                LDMX4(af[am][0], af[am][1], af[am][2], af[am][3], addr);
            }
            uint32_t bf[8][2];
#pragma unroll
            for (int bn = 0; bn < 4; bn++) {
                int trow = wn * 64 + bn * 16 + (tile >> 1) * 8 + r;
                uint32_t addr = sB[s] + trow * LDSS + kk * 32 + (tile & 1) * 16;
                LDMX4(bf[2 * bn][0], bf[2 * bn][1], bf[2 * bn + 1][0], bf[2 * bn + 1][1], addr);
            }
#pragma unroll
            for (int am = 0; am < 2; am++)
#pragma unroll
                for (int bn = 0; bn < 8; bn++) MMA16816(acc[am][bn], af[am], bf[bn]);
        }
        __syncthreads();
    }

    // epilogue (all lanes execute; stores/atomics predicated on valid)
#pragma unroll
    for (int am = 0; am < 2; am++) {
        int r0 = m0 + wm * 32 + am * 16 + (lane >> 2);
#pragma unroll
        for (int half = 0; half < 2; half++) {
            int row = r0 + half * 8;
            bool valid = row < M;
            float s0 = 0.f, s1 = 0.f;
#pragma unroll
            for (int bn = 0; bn < 8; bn++) {
                int col = n0 + wn * 64 + bn * 8 + (lane & 3) * 2;
                float v0 = acc[am][bn][2 * half], v1 = acc[am][bn][2 * half + 1];
                if (EPI == 0) {
                    if (valid)
                        *(__half2*)(Y + (size_t)row * DH + col) = __floats2half2_rn(v0, v1);
                } else {
                    float2 bs = *(const float2*)(bias + col);
                    v0 = fmaxf(v0 + bs.x, 0.f);
                    v1 = fmaxf(v1 + bs.y, 0.f);
                    if (WA2 && valid)
                        *(__half2*)(A2out + (size_t)row * DH + col) = __floats2half2_rn(v0, v1);
                    if (HEAD) {
                        float4 w = *(const float4*)(Wout + 2 * col);
                        s0 = fmaf(v0, w.x, fmaf(v1, w.z, s0));
                        s1 = fmaf(v0, w.y, fmaf(v1, w.w, s1));
                    }
                }
            }
            if (HEAD) {
                s0 += __shfl_xor_sync(0xffffffffu, s0, 1);
                s0 += __shfl_xor_sync(0xffffffffu, s0, 2);
                s1 += __shfl_xor_sync(0xffffffffu, s1, 1);
                s1 += __shfl_xor_sync(0xffffffffu, s1, 2);
                if (valid && (lane & 3) == 0) {
                    atomicAdd(out + 2 * row, s0);
                    atomicAdd(out + 2 * row + 1, s1);
                }
            }
        }
    }
}

// ---------------- fused aggregation (fp16 gather, fp32 accum) + bias + BN + ReLU -> fp16 ----------------
__global__ void k_agg(const __half* __restrict__ Y, const float* __restrict__ bias,
                      const float* __restrict__ gamma, const float* __restrict__ beta,
                      const float* __restrict__ mean, const float* __restrict__ var,
                      __half* __restrict__ A2out) {
    int n = blockIdx.x, t = threadIdx.x;
    int c = t * 4;
    int beg = g_offs[n], end = g_offs[n + 1];
    float4 acc;
    {
        uint2 raw = *(const uint2*)(Y + (size_t)n * DH + c);
        float2 a = __half22float2(*(__half2*)&raw.x);
        float2 b = __half22float2(*(__half2*)&raw.y);
        acc = make_float4(a.x, a.y, b.x, b.y);
    }
    float4 bs = *(const float4*)(bias + c);
    acc.x += bs.x; acc.y += bs.y; acc.z += bs.z; acc.w += bs.w;
    int i = beg;
    for (; i + 4 <= end; i += 4) {
        int s0 = g_csr[i], s1 = g_csr[i + 1], s2 = g_csr[i + 2], s3 = g_csr[i + 3];
        uint2 r0 = *(const uint2*)(Y + (size_t)s0 * DH + c);
        uint2 r1 = *(const uint2*)(Y + (size_t)s1 * DH + c);
        uint2 r2 = *(const uint2*)(Y + (size_t)s2 * DH + c);
        uint2 r3 = *(const uint2*)(Y + (size_t)s3 * DH + c);
        float2 a0 = __half22float2(*(__half2*)&r0.x), b0 = __half22float2(*(__half2*)&r0.y);
        float2 a1 = __half22float2(*(__half2*)&r1.x), b1 = __half22float2(*(__half2*)&r1.y);
        float2 a2 = __half22float2(*(__half2*)&r2.x), b2 = __half22float2(*(__half2*)&r2.y);
        float2 a3 = __half22float2(*(__half2*)&r3.x), b3 = __half22float2(*(__half2*)&r3.y);
        acc.x += (a0.x + a1.x) + (a2.x + a3.x);
        acc.y += (a0.y + a1.y) + (a2.y + a3.y);
        acc.z += (b0.x + b1.x) + (b2.x + b3.x);
        acc.w += (b0.y + b1.y) + (b2.y + b3.y);
    }
    for (; i < end; i++) {
        int s = g_csr[i];
        uint2 raw = *(const uint2*)(Y + (size_t)s * DH + c);
        float2 a = __half22float2(*(__half2*)&raw.x);
        float2 b = __half22float2(*(__half2*)&raw.y);
        acc.x += a.x; acc.y += a.y; acc.z += b.x; acc.w += b.y;
    }
    float4 mn = *(const float4*)(mean + c);
    float4 vr = *(const float4*)(var + c);
    float4 gm = *(const float4*)(gamma + c);
    float4 bt = *(const float4*)(beta + c);
    acc.x = fmaxf(fmaf((acc.x - mn.x) * rsqrtf(vr.x + BN_EPS), gm.x, bt.x), 0.f);
    acc.y = fmaxf(fmaf((acc.y - mn.y) * rsqrtf(vr.y + BN_EPS), gm.y, bt.y), 0.f);
    acc.z = fmaxf(fmaf((acc.z - mn.z) * rsqrtf(vr.z + BN_EPS), gm.z, bt.z), 0.f);
    acc.w = fmaxf(fmaf((acc.w - mn.w) * rsqrtf(vr.w + BN_EPS), gm.w, bt.w), 0.f);
    __half2* p = (__half2*)(A2out + (size_t)n * DH + c);
    p[0] = __floats2half2_rn(acc.x, acc.y);
    p[1] = __floats2half2_rn(acc.z, acc.w);
}

// ---------------- launch ----------------
extern "C" void kernel_launch(void* const* d_in, const int* in_sizes, int n_in,
                              void* d_out, int out_size) {
    const float* x    = (const float*)d_in[0];
    const void*  ei   = d_in[1];
    const float* W1a  = (const float*)d_in[2];
    const float* b1a  = (const float*)d_in[3];
    const float* g1   = (const float*)d_in[4];
    const float* be1  = (const float*)d_in[5];
    const float* m1   = (const float*)d_in[6];
    const float* v1   = (const float*)d_in[7];
    const float* W1b  = (const float*)d_in[8];
    const float* b1b  = (const float*)d_in[9];
    const float* W2a  = (const float*)d_in[10];
    const float* b2a  = (const float*)d_in[11];
    const float* g2   = (const float*)d_in[12];
    const float* be2  = (const float*)d_in[13];
    const float* m2   = (const float*)d_in[14];
    const float* v2   = (const float*)d_in[15];
    const float* W2b  = (const float*)d_in[16];
    const float* b2b  = (const float*)d_in[17];
    const float* Wout = (const float*)d_in[18];
    const float* bout = (const float*)d_in[19];
    float* out = (float*)d_out;

    int E = in_sizes[1] / 2;
    int K1 = in_sizes[2] / DH;  // 768
    int M = in_sizes[0] / K1;   // 50000

    __half *Y, *A2, *A2b, *B2base;
    cudaGetSymbolAddress((void**)&Y, g_Y);
    cudaGetSymbolAddress((void**)&A2, g_A2);
    cudaGetSymbolAddress((void**)&A2b, g_A2b);
    cudaGetSymbolAddress((void**)&B2base, g_B2);
    __half* B2_1a = B2base;
    __half* B2_1b = B2base + (size_t)DH * KMAX;
    __half* B2_2a = B2base + 2 * (size_t)DH * KMAX;
    __half* B2_2b = B2base + 3 * (size_t)DH * KMAX;

    cudaFuncSetAttribute(k_gemm_mma<0, 0, 0>, cudaFuncAttributeMaxDynamicSharedMemorySize, DSM_REQ);
    cudaFuncSetAttribute(k_gemm_mma<1, 1, 0>, cudaFuncAttributeMaxDynamicSharedMemorySize, DSM_REQ);
    cudaFuncSetAttribute(k_gemm_mma<1, 0, 1>, cudaFuncAttributeMaxDynamicSharedMemorySize, DSM_REQ);

    // prep: detect | convW | setup | convA in one launch
    int wtot = K1 * 512 + 3 * 512 * 512;
    int nbW = (wtot + 255) / 256;
    int nbS = (2 * M + 255) / 256;
    int nbA = (M * (K1 / 4) + 255) / 256;
    k_prep<<<1 + nbW + nbS + nbA, 256>>>((const unsigned*)ei, E,
                                         W1a, W1b, W2a, W2b, B2base, K1,
                                         out, bout, x, A2, M);

    // CSR build
    k_count<<<(E + 255) / 256, 256>>>(ei, E);
    int NB = (M + 1023) / 1024;
    k_scan1<<<NB, 1024>>>(M);
    k_scan3<<<NB, 1024>>>(M, E);
    k_fill<<<(E + 255) / 256, 256>>>(ei, E);

    dim3 gg(4, (M + 127) / 128);

    // Layer 1: (x + agg(x))@W1a + b1a == x@W1a + segsum((x@W1a)[src]) + b1a
    k_gemm_mma<0, 0, 0><<<gg, 256, DSM_REQ>>>(A2, B2_1a, nullptr, Y, nullptr, nullptr, nullptr, M, K1);
    k_agg<<<M, 128>>>(Y, b1a, g1, be1, m1, v1, A2b);
    k_gemm_mma<1, 1, 0><<<gg, 256, DSM_REQ>>>(A2b, B2_1b, b1b, nullptr, A2, nullptr, nullptr, M, DH);

    // Layer 2
    k_gemm_mma<0, 0, 0><<<gg, 256, DSM_REQ>>>(A2, B2_2a, nullptr, Y, nullptr, nullptr, nullptr, M, DH);
    k_agg<<<M, 128>>>(Y, b2a, g2, be2, m2, v2, A2b);
    // final GEMM: fused bias+ReLU+head (out += relu(acc+b) @ Wout)
    k_gemm_mma<1, 0, 1><<<gg, 256, DSM_REQ>>>(A2b, B2_2b, b2b, nullptr, nullptr, Wout, out, M, DH);
}